// round 1
// baseline (speedup 1.0000x reference)
#include <cuda_runtime.h>
#include <cuda_bf16.h>
#include <cstddef>

// Problem constants
#define NHh 8
#define NLl 4
#define NPp 4
#define HDd 32
#define Dm  256
#define Bb  2
#define Ss  13294          // 100*100 + 50*50 + 25*25 + 13*13
#define LQ  13294
#define MROWS (Bb * LQ)    // 26588

// Scratch (allocation-free: __device__ globals)
__device__ float g_val [Bb * Ss * Dm];   // projected value, (B,S,NH,HD) flattened
__device__ float g_off [Bb * LQ * Dm];   // sampling offsets, (B,L,256)
__device__ float g_attn[Bb * LQ * 128];  // attention logits, (B,L,128)
__device__ float g_acc [Bb * LQ * Dm];   // pre-output accumulator, (B,L,256)

// ---------------------------------------------------------------------------
// Tiled fp32 GEMM: C[M,N] = A[M,K] @ B[K,N] + bias[N]
// 64x64 block tile, BK=16, 256 threads, 4x4 register microtile, float4 loads.
// N must be a multiple of 64 and K a multiple of 16 (true here: N in {128,256}, K=256).
// ---------------------------------------------------------------------------
__global__ __launch_bounds__(256) void gemm_bias_kernel(
    const float* __restrict__ A, const float* __restrict__ Bw,
    const float* __restrict__ bias, float* __restrict__ C,
    int M, int N, int K)
{
    __shared__ float As[16][65];   // [k][m], padded to dodge bank conflicts
    __shared__ float Bs[16][68];   // [k][n], padded (stride keeps 16B alignment)

    const int tid = threadIdx.x;
    const int tx  = tid & 15;      // -> 4 output cols
    const int ty  = tid >> 4;      // -> 4 output rows
    const int bm  = blockIdx.y * 64;
    const int bn  = blockIdx.x * 64;

    const int aRow = tid >> 2, aC4 = tid & 3;    // A tile: 64 rows x 16 k (float4 along k)
    const int bRow = tid >> 4, bC4 = tid & 15;   // B tile: 16 k x 64 cols (float4 along n)

    float acc[4][4] = {};

    for (int k0 = 0; k0 < K; k0 += 16) {
        float4 av = make_float4(0.f, 0.f, 0.f, 0.f);
        const int gr = bm + aRow;
        if (gr < M)
            av = *reinterpret_cast<const float4*>(A + (size_t)gr * K + k0 + aC4 * 4);
        As[aC4 * 4 + 0][aRow] = av.x;
        As[aC4 * 4 + 1][aRow] = av.y;
        As[aC4 * 4 + 2][aRow] = av.z;
        As[aC4 * 4 + 3][aRow] = av.w;

        const float4 bv = *reinterpret_cast<const float4*>(
            Bw + (size_t)(k0 + bRow) * N + bn + bC4 * 4);
        *reinterpret_cast<float4*>(&Bs[bRow][bC4 * 4]) = bv;

        __syncthreads();

        #pragma unroll
        for (int k = 0; k < 16; k++) {
            float a[4], bf[4];
            #pragma unroll
            for (int i = 0; i < 4; i++) a[i]  = As[k][ty * 4 + i];
            #pragma unroll
            for (int j = 0; j < 4; j++) bf[j] = Bs[k][tx * 4 + j];
            #pragma unroll
            for (int i = 0; i < 4; i++)
                #pragma unroll
                for (int j = 0; j < 4; j++)
                    acc[i][j] += a[i] * bf[j];
        }
        __syncthreads();
    }

    #pragma unroll
    for (int i = 0; i < 4; i++) {
        const int r = bm + ty * 4 + i;
        if (r < M) {
            #pragma unroll
            for (int j = 0; j < 4; j++) {
                const int c = bn + tx * 4 + j;
                C[(size_t)r * N + c] = acc[i][j] + bias[c];
            }
        }
    }
}

// ---------------------------------------------------------------------------
// Sampling kernel: one warp per (b, q, h). Lane = channel (HD=32).
// Computes softmax over the 16 (level, point) logits, then accumulates
// bilinear zero-padded samples. Every corner gather is a coalesced 128B line.
// ---------------------------------------------------------------------------
__global__ __launch_bounds__(256) void sample_kernel(
    const float* __restrict__ refp,   // (B, L, NL, 2)
    const float* __restrict__ val,    // (B, S, 256)
    const float* __restrict__ off,    // (B, L, 256)
    const float* __restrict__ attn,   // (B, L, 128)
    float* __restrict__ out_acc)      // (B, L, 256)
{
    const int lH[4] = {100, 50, 25, 13};
    const int lW[4] = {100, 50, 25, 13};
    const int lS[4] = {0, 10000, 12500, 13125};

    const int g = blockIdx.x * 8 + (threadIdx.x >> 5);
    if (g >= Bb * LQ * NHh) return;
    const int lane = threadIdx.x & 31;
    const int h    = g & 7;
    const int bq   = g >> 3;            // b*LQ + q
    const int b    = bq / LQ;

    // softmax over 16 logits (redundant per-lane; L1 broadcast)
    const float* at = attn + (size_t)bq * 128 + h * 16;
    float e[16];
    float mx = at[0];
    #pragma unroll
    for (int j = 1; j < 16; j++) mx = fmaxf(mx, at[j]);
    float s = 0.f;
    #pragma unroll
    for (int j = 0; j < 16; j++) { e[j] = __expf(at[j] - mx); s += e[j]; }
    const float inv = 1.0f / s;

    const float* of = off  + (size_t)bq * 256 + h * 32;
    const float* rp = refp + (size_t)bq * (NLl * 2);

    float acc = 0.f;

    #pragma unroll
    for (int l = 0; l < 4; l++) {
        const int H = lH[l], W = lW[l];
        const float* vb = val + (size_t)(b * Ss + lS[l]) * 256 + h * 32 + lane;
        const float rx = rp[l * 2 + 0] * (float)W - 0.5f;
        const float ry = rp[l * 2 + 1] * (float)H - 0.5f;

        #pragma unroll
        for (int p = 0; p < 4; p++) {
            const float x = rx + of[l * 8 + p * 2 + 0];
            const float y = ry + of[l * 8 + p * 2 + 1];
            const float wgt = e[l * 4 + p] * inv;

            const float fx0 = floorf(x), fy0 = floorf(y);
            const int x0 = (int)fx0, y0 = (int)fy0;
            const float wx1 = x - fx0, wy1 = y - fy0;
            const float wx0 = 1.f - wx1, wy0 = 1.f - wy1;

            const bool xin0 = (x0 >= 0)     && (x0 < W);
            const bool xin1 = (x0 + 1 >= 0) && (x0 + 1 < W);
            const bool yin0 = (y0 >= 0)     && (y0 < H);
            const bool yin1 = (y0 + 1 >= 0) && (y0 + 1 < H);

            float v00 = 0.f, v10 = 0.f, v01 = 0.f, v11 = 0.f;
            if (yin0) {
                const int r0 = y0 * W;
                if (xin0) v00 = vb[(size_t)(r0 + x0)     * 256];
                if (xin1) v10 = vb[(size_t)(r0 + x0 + 1) * 256];
            }
            if (yin1) {
                const int r1 = (y0 + 1) * W;
                if (xin0) v01 = vb[(size_t)(r1 + x0)     * 256];
                if (xin1) v11 = vb[(size_t)(r1 + x0 + 1) * 256];
            }
            acc += wgt * (wy0 * (wx0 * v00 + wx1 * v10) +
                          wy1 * (wx0 * v01 + wx1 * v11));
        }
    }

    out_acc[(size_t)bq * 256 + h * 32 + lane] = acc;
}

// ---------------------------------------------------------------------------
// Launch
// ---------------------------------------------------------------------------
extern "C" void kernel_launch(void* const* d_in, const int* in_sizes, int n_in,
                              void* d_out, int out_size)
{
    const float* query  = (const float*)d_in[0];
    const float* refp   = (const float*)d_in[1];
    const float* value  = (const float*)d_in[2];
    const float* W_val  = (const float*)d_in[3];
    const float* b_val  = (const float*)d_in[4];
    const float* W_off  = (const float*)d_in[5];
    const float* b_off  = (const float*)d_in[6];
    const float* W_attn = (const float*)d_in[7];
    const float* b_attn = (const float*)d_in[8];
    const float* W_out  = (const float*)d_in[9];
    const float* b_out  = (const float*)d_in[10];
    float* out = (float*)d_out;

    float *pval, *poff, *pattn, *pacc;
    cudaGetSymbolAddress((void**)&pval,  g_val);
    cudaGetSymbolAddress((void**)&poff,  g_off);
    cudaGetSymbolAddress((void**)&pattn, g_attn);
    cudaGetSymbolAddress((void**)&pacc,  g_acc);

    const dim3 blk(256);
    const dim3 g256(256 / 64, (MROWS + 63) / 64);
    const dim3 g128(128 / 64, (MROWS + 63) / 64);

    // 1. val = value @ W_val + b_val          (B*S, 256)
    gemm_bias_kernel<<<g256, blk>>>(value, W_val, b_val, pval, MROWS, 256, 256);
    // 2. offsets = query @ W_off + b_off      (B*L, 256)
    gemm_bias_kernel<<<g256, blk>>>(query, W_off, b_off, poff, MROWS, 256, 256);
    // 3. attn logits = query @ W_attn + b_attn (B*L, 128)
    gemm_bias_kernel<<<g128, blk>>>(query, W_attn, b_attn, pattn, MROWS, 128, 256);
    // 4. softmax + deformable bilinear sampling -> g_acc
    const int nwarps = MROWS * NHh;            // 212704
    sample_kernel<<<(nwarps + 7) / 8, blk>>>(refp, pval, poff, pattn, pacc);
    // 5. out = g_acc @ W_out + b_out
    gemm_bias_kernel<<<g256, blk>>>(pacc, W_out, b_out, out, MROWS, 256, 256);
}